// round 16
// baseline (speedup 1.0000x reference)
#include <cuda_runtime.h>
#include <cuda_bf16.h>

#define N_G   4096
#define IMG_W 512
#define TILE  64
#define BLOCK 128
#define NB    1184                   // 148 x 8 blocks (128 thr, <=64 regs) — all co-resident
#define NSUB  1024                   // 64 tiles x 16 subtiles (16x16 px)
#define NBUCK 1024
#define BCAP  64
#define EXPSCALE (-0.72134752044f)   // -0.5 * log2(e)
#define FTHR     (-6.64385619f)      // -2*log2(100)

typedef unsigned long long u64;

__device__ float4 g_geo[N_G];        // px, py, radius (binning)
__device__ float4 g_la [N_G];        // px, py, ca', cbc'
__device__ float4 g_lb [N_G];        // cd', log2(op), ha, r
__device__ float4 g_lc [N_G];        // g, b, hc, 0
__device__ int    g_hist[NBUCK];     // zeroed at end of each launch
__device__ u64    g_bkey[NBUCK * BCAP];

__device__ float4 t_la[64 * N_G], t_lb[64 * N_G], t_lc[64 * N_G];
__device__ int    t_cnt[64];
__device__ int    c3a[64][8];
__device__ int    t_ready[64];

__device__ unsigned g_bar;
__device__ unsigned g_q;

__device__ __forceinline__ float ex2f(float x) {
    float y; asm("ex2.approx.f32 %0, %1;" : "=f"(y) : "f"(x)); return y;
}
__device__ __forceinline__ float rcpf(float x) {
    float y; asm("rcp.approx.f32 %0, %1;" : "=f"(y) : "f"(x)); return y;
}
__device__ __forceinline__ u64 pk2(float lo, float hi) {
    u64 r; asm("mov.b64 %0, {%1, %2};" : "=l"(r) : "f"(lo), "f"(hi)); return r;
}
__device__ __forceinline__ void upk2(float& lo, float& hi, u64 v) {
    asm("mov.b64 {%0, %1}, %2;" : "=f"(lo), "=f"(hi) : "l"(v));
}
__device__ __forceinline__ u64 fma2(u64 a, u64 b, u64 c) {
    u64 d; asm("fma.rn.f32x2 %0, %1, %2, %3;" : "=l"(d) : "l"(a), "l"(b), "l"(c)); return d;
}
__device__ __forceinline__ u64 mul2(u64 a, u64 b) {
    u64 d; asm("mul.rn.f32x2 %0, %1, %2;" : "=l"(d) : "l"(a), "l"(b)); return d;
}
__device__ __forceinline__ int dbucket(float d) {
    int b = (int)((d - 0.1f) * 102.4f);
    return max(0, min(NBUCK - 1, b));
}

struct SM {
    float4     n0[BLOCK];            // px, py, ca', cbc'
    float2     n1[BLOCK];            // lop2, -gP
    ulonglong2 p0[BLOCK];            // cd2, (gP*colr)2      (D: p0..p1 = s_h)
    ulonglong2 p1[BLOCK];
    ulonglong2 p2[BLOCK];            // gapSr2, gapSg2       (D: p2..p3 = s_bs)
    ulonglong2 p3[BLOCK];
    float      sSr[BLOCK], sSg[BLOCK], sSb[BLOCK], sP[BLOCK];
    int        wsum[4];
    float      wsf[16];
    float      wsf2[20];             // [w*4..] exclusive warp prefixes; [16..19] totals
    int        wsum2[4];
    int        sncnt;
    float      tailSr, tailSg, tailSb, tailP;
    int        item;
};

__device__ __forceinline__ int scan_bool(bool p, int* wsum, int& tot) {
    __syncthreads();
    const unsigned bits = __ballot_sync(0xffffffffu, p);
    const int lane = threadIdx.x & 31, wd = threadIdx.x >> 5;
    if (lane == 0) wsum[wd] = __popc(bits);
    __syncthreads();
    int off = 0, t = 0;
#pragma unroll
    for (int w = 0; w < 4; w++) { int c = wsum[w]; if (w < wd) off += c; t += c; }
    tot = t;
    return off + __popc(bits & ((1u << lane) - 1u));
}

__device__ __forceinline__ void grid_sync() {
    __syncthreads();
    if (threadIdx.x == 0) {
        __threadfence();
        unsigned v = atomicAdd(&g_bar, 1u);
        unsigned target = (v / NB + 1u) * NB;
        while (*(volatile unsigned*)&g_bar < target) { }
        __threadfence();
    }
    __syncthreads();
}

__global__ void __launch_bounds__(BLOCK, 8)
fused_kernel(const float* __restrict__ pos2d, const float* __restrict__ cov2d,
             const float* __restrict__ opacity, const float* __restrict__ color,
             float* __restrict__ out)
{
    __shared__ SM sm;
    const int tid = threadIdx.x;
    const int bid = blockIdx.x;
    const int lane = tid & 31, wd = tid >> 5;
    const unsigned FULL = 0xffffffffu;

    // ---------- Phase B: bucket scatter (blocks 0..31) + counter reset ---------
    if (bid < 32) {
        const int i = bid * BLOCK + tid;
        const float d = pos2d[i * 3 + 2];
        const int b = dbucket(d);
        const int slot = atomicAdd(&g_hist[b], 1);
        if (slot < BCAP)
            g_bkey[(b << 6) + slot] = ((u64)__float_as_uint(d) << 32) | (unsigned)i;
    } else if (bid == 32) {
        for (int k = tid; k < 64 * 8; k += BLOCK) ((int*)c3a)[k] = 0;
        for (int k = tid; k < 64; k += BLOCK) t_ready[k] = 0;
        if (tid == 0) g_q = 0;
    }
    grid_sync();

    // ---------- Phase D: prefix + exact rank + params + bins (blocks 0..255) ---
    if (bid < 256) {
        int* s_h  = (int*)sm.p0;    // 1024 ints (p0..p1 = 4KB)
        int* s_bs = (int*)sm.p2;    // 1024 ints (p2..p3 = 4KB)
        for (int k = tid; k < NBUCK; k += BLOCK) s_h[k] = min(g_hist[k], BCAP);
        __syncthreads();
        const int t8 = tid * 8;
        int h[8], sum8 = 0;
#pragma unroll
        for (int k = 0; k < 8; k++) { h[k] = s_h[t8 + k]; sum8 += h[k]; }
        int inc = sum8;
#pragma unroll
        for (int d = 1; d < 32; d <<= 1) {
            const int u = __shfl_up_sync(FULL, inc, d);
            if (lane >= d) inc += u;
        }
        if (lane == 31) sm.wsum[wd] = inc;
        __syncthreads();
        int woff = 0;
#pragma unroll
        for (int w = 0; w < 4; w++) if (w < wd) woff += sm.wsum[w];
        int running = woff + inc - sum8;
#pragma unroll
        for (int k = 0; k < 8; k++) { s_bs[t8 + k] = running; running += h[k]; }
        __syncthreads();

        if (tid < 16) {
            const int i = bid * 16 + tid;
            const float dep = pos2d[i * 3 + 2];
            const u64 ki = ((u64)__float_as_uint(dep) << 32) | (unsigned)i;
            const int bk = dbucket(dep);
            const int cnt = s_h[bk];
            int rank = s_bs[bk];
#pragma unroll 4
            for (int j = 0; j < cnt; j++)
                rank += (g_bkey[(bk << 6) + j] < ki) ? 1 : 0;

            const float a = cov2d[i * 4 + 0];
            const float b = cov2d[i * 4 + 1];
            const float c = cov2d[i * 4 + 2];
            const float d = cov2d[i * 4 + 3];
            const float trace = a + d;
            const float det   = a * d - b * c;
            const float term2 = 0.5f * sqrtf(fmaxf(trace * trace - 4.0f * det, 0.0f));
            const float radius = 3.0f * sqrtf(fmaxf(0.5f * trace - term2, 0.5f * trace + term2));
            const float inv_det = 1.0f / det;

            const float px = pos2d[i * 3 + 0];
            const float py = pos2d[i * 3 + 1];
            const float lop2 = __log2f(opacity[i]);
            const float cr = fmaxf(color[i * 3 + 0] + 0.5f, 0.0f);
            const float cg = fmaxf(color[i * 3 + 1] + 0.5f, 0.0f);
            const float cb = fmaxf(color[i * 3 + 2] + 0.5f, 0.0f);

            const float cap  = EXPSCALE * d * inv_det;
            const float cbcp = EXPSCALE * -(b + c) * inv_det;
            const float cdp  = EXPSCALE * a * inv_det;
            const float hc = 0.5f * (b + c) / a;
            const float ha = 0.5f * (b + c) / d;

            g_geo[rank] = make_float4(px, py, radius, 0.0f);
            g_la [rank] = make_float4(px, py, cap, cbcp);
            g_lb [rank] = make_float4(cdp, lop2, ha, cr);
            g_lc [rank] = make_float4(cg, cb, hc, 0.0f);

            const int ch = rank >> 9;
            const int tx0 = max(0, (int)floorf((px - radius) * (1.f / 64.f)) - 1);
            const int tx1 = min(7, (int)floorf((px + radius) * (1.f / 64.f)) + 1);
            const int ty0 = max(0, (int)floorf((py - radius) * (1.f / 64.f)) - 1);
            const int ty1 = min(7, (int)floorf((py + radius) * (1.f / 64.f)) + 1);
            for (int tx = tx0; tx <= tx1; tx++) {
                const float left = (float)(tx * TILE);
                if (!((px + radius >= left) && (px - radius < left + (float)TILE))) continue;
                for (int ty = ty0; ty <= ty1; ty++) {
                    const float top = (float)(ty * TILE);
                    if ((py + radius >= top) && (py - radius < top + (float)TILE))
                        atomicAdd(&c3a[(tx << 3) | ty][ch], 1);
                }
            }
        }
    }
    grid_sync();

    // ---------- Phase 3: ordered compaction (blocks 0..511); 512 zeroes hist ---
    if (bid < 512) {
        const int tile = bid >> 3, ch = bid & 7;
        const float left = (float)((tile >> 3) * TILE);
        const float top  = (float)((tile & 7) * TILE);
        int offset = 0, total = 0;
#pragma unroll
        for (int c = 0; c < 8; c++) {
            const int cc = c3a[tile][c];
            if (c < ch) offset += cc;
            total += cc;
        }
        if (ch == 0 && tid == 0) t_cnt[tile] = total;
        int outbase = offset;
#pragma unroll
        for (int r = 0; r < 4; r++) {
            const int g = ch * 512 + r * BLOCK + tid;
            const float4 geo = g_geo[g];
            const bool v = (geo.x + geo.z >= left) && (geo.x - geo.z < left + (float)TILE) &&
                           (geo.y + geo.z >= top)  && (geo.y - geo.z < top  + (float)TILE);
            int tot;
            const int pos = scan_bool(v, sm.wsum, tot);
            if (v) {
                const int o = tile * N_G + outbase + pos;
                t_la[o] = g_la[g];
                t_lb[o] = g_lb[g];
                t_lc[o] = g_lc[g];
            }
            outbase += tot;
        }
        __syncthreads();
        if (tid == 0) {
            __threadfence();
            atomicAdd(&t_ready[tile], 1);
        }
    } else if (bid == 512) {
        for (int k = tid; k < NBUCK; k += BLOCK) g_hist[k] = 0;
    }

    // ---------- Phase 4: work-stealing render over 1024 subtiles (16x16) -------
    for (;;) {
        __syncthreads();
        if (tid == 0) sm.item = (int)atomicAdd(&g_q, 1u);
        __syncthreads();
        const int sub = sm.item;
        if (sub >= NSUB) break;

        const int ptile = sub >> 4, si = sub & 15;
        if (tid == 0) {
            while (*(volatile int*)&t_ready[ptile] < 8) __nanosleep(64);
            __threadfence();
        }
        __syncthreads();

        const int X0 = (ptile >> 3) * TILE + (si >> 2) * 16;
        const int Y0 = (ptile & 7) * TILE + (si & 3) * 16;
        const float rx0 = (float)X0, rx1 = (float)(X0 + 15);
        const float ry0 = (float)Y0, ry1 = (float)(Y0 + 15);

        const int Xi  = X0 + (tid >> 3);
        const int Yi0 = Y0 + (tid & 7);
        const int Yi1 = Yi0 + 8;
        const float X = (float)Xi, Yf0 = (float)Yi0, Yf1 = (float)Yi1;

        const int cnt = t_cnt[ptile];
        const float4* __restrict__ LA = t_la + ptile * N_G;
        const float4* __restrict__ LB = t_lb + ptile * N_G;
        const float4* __restrict__ LC = t_lc + ptile * N_G;

        u64 T2  = pk2(1.f, 1.f);
        u64 CR2 = pk2(0.f, 0.f), CG2 = CR2, CB2 = CR2;
        bool dead = false;

        for (int c0 = 0; c0 < cnt; c0 += BLOCK) {
            const int L = cnt - c0;
            const bool validg = tid < L;
            float4 la = make_float4(0,0,0,0), lb = make_float4(0,0,0,0), lc = make_float4(0,0,0,0);
            bool isfar = false;
            if (validg) {
                la = LA[c0 + tid]; lb = LB[c0 + tid]; lc = LC[c0 + tid];
                const float dxlo = rx0 - la.x, dxhi = rx1 - la.x;
                const float dylo = ry0 - la.y, dyhi = ry1 - la.y;
                const bool inside = (dxlo <= 0.f) && (dxhi >= 0.f) &&
                                    (dylo <= 0.f) && (dyhi >= 0.f);
                float qsm = 0.0f;
                if (!inside) {
                    const float hc = lc.z, ha = lb.z;
                    float dys = fminf(fmaxf(hc * dxlo, dylo), dyhi);
                    qsm = fmaf(fmaf(la.w, dys, la.z * dxlo), dxlo, lb.x * dys * dys);
                    dys = fminf(fmaxf(hc * dxhi, dylo), dyhi);
                    qsm = fmaxf(qsm, fmaf(fmaf(la.w, dys, la.z * dxhi), dxhi, lb.x * dys * dys));
                    float dxs = fminf(fmaxf(ha * dylo, dxlo), dxhi);
                    qsm = fmaxf(qsm, fmaf(fmaf(la.w, dxs, lb.x * dylo), dylo, la.z * dxs * dxs));
                    dxs = fminf(fmaxf(ha * dyhi, dxlo), dxhi);
                    qsm = fmaxf(qsm, fmaf(fmaf(la.w, dxs, lb.x * dyhi), dyhi, la.z * dxs * dxs));
                }
                isfar = qsm < (FTHR - lb.y);
            }
            const bool isnear = validg && !isfar;

            float aSr = 0.f, aSg = 0.f, aSb = 0.f, aP = 1.f;
            if (isfar) { aSr = 0.01f * lb.w; aSg = 0.01f * lc.x; aSb = 0.01f * lc.y; aP = 0.99f; }

            float vSr = aSr, vSg = aSg, vSb = aSb, vP = aP;
#pragma unroll
            for (int d = 1; d < 32; d <<= 1) {
                const float uSr = __shfl_up_sync(FULL, vSr, d);
                const float uSg = __shfl_up_sync(FULL, vSg, d);
                const float uSb = __shfl_up_sync(FULL, vSb, d);
                const float uP  = __shfl_up_sync(FULL, vP,  d);
                if (lane >= d) {
                    vSr = fmaf(uP, vSr, uSr);
                    vSg = fmaf(uP, vSg, uSg);
                    vSb = fmaf(uP, vSb, uSb);
                    vP *= uP;
                }
            }
            const unsigned nbits = __ballot_sync(FULL, isnear);
            if (lane == 31) {
                sm.wsf[wd*4+0] = vSr; sm.wsf[wd*4+1] = vSg;
                sm.wsf[wd*4+2] = vSb; sm.wsf[wd*4+3] = vP;
                sm.wsum[wd] = __popc(nbits);
            }
            __syncthreads();                                   // bar 1

            if (wd == 0) {
                float wSr = 0.f, wSg = 0.f, wSb = 0.f, wP = 1.f;
                int wc = 0;
                if (lane < 4) {
                    wSr = sm.wsf[lane*4+0]; wSg = sm.wsf[lane*4+1];
                    wSb = sm.wsf[lane*4+2]; wP  = sm.wsf[lane*4+3];
                    wc  = sm.wsum[lane];
                }
#pragma unroll
                for (int d = 1; d < 4; d <<= 1) {
                    const float uSr = __shfl_up_sync(FULL, wSr, d);
                    const float uSg = __shfl_up_sync(FULL, wSg, d);
                    const float uSb = __shfl_up_sync(FULL, wSb, d);
                    const float uP  = __shfl_up_sync(FULL, wP,  d);
                    const int   uc  = __shfl_up_sync(FULL, wc,  d);
                    if (lane >= d) {
                        wSr = fmaf(uP, wSr, uSr);
                        wSg = fmaf(uP, wSg, uSg);
                        wSb = fmaf(uP, wSb, uSb);
                        wP *= uP;
                        wc += uc;
                    }
                }
                float xSr = __shfl_up_sync(FULL, wSr, 1);
                float xSg = __shfl_up_sync(FULL, wSg, 1);
                float xSb = __shfl_up_sync(FULL, wSb, 1);
                float xP  = __shfl_up_sync(FULL, wP,  1);
                int   xc  = __shfl_up_sync(FULL, wc,  1);
                if (lane == 0) { xSr = 0.f; xSg = 0.f; xSb = 0.f; xP = 1.f; xc = 0; }
                if (lane < 4) {
                    sm.wsf2[lane*4+0] = xSr; sm.wsf2[lane*4+1] = xSg;
                    sm.wsf2[lane*4+2] = xSb; sm.wsf2[lane*4+3] = xP;
                    sm.wsum2[lane] = xc;
                }
                if (lane == 3) {
                    sm.wsf2[16] = wSr; sm.wsf2[17] = wSg;
                    sm.wsf2[18] = wSb; sm.wsf2[19] = wP;
                    sm.sncnt = wc;
                }
            }
            __syncthreads();                                   // bar 2

            const float oSr = sm.wsf2[wd*4+0], oSg = sm.wsf2[wd*4+1];
            const float oSb = sm.wsf2[wd*4+2], oP  = sm.wsf2[wd*4+3];
            const int ioff = sm.wsum2[wd];
            const int ncnt = sm.sncnt;

            float eSr = __shfl_up_sync(FULL, vSr, 1);
            float eSg = __shfl_up_sync(FULL, vSg, 1);
            float eSb = __shfl_up_sync(FULL, vSb, 1);
            float eP  = __shfl_up_sync(FULL, vP,  1);
            if (lane == 0) { eSr = 0.f; eSg = 0.f; eSb = 0.f; eP = 1.f; }
            const float ESr = fmaf(oP, eSr, oSr);
            const float ESg = fmaf(oP, eSg, oSg);
            const float ESb = fmaf(oP, eSb, oSb);
            const float EP  = oP * eP;

            const int nidx = ioff + __popc(nbits & ((1u << lane) - 1u));
            if (isnear) {
                sm.sSr[nidx] = ESr; sm.sSg[nidx] = ESg; sm.sSb[nidx] = ESb; sm.sP[nidx] = EP;
                sm.n0[nidx] = la;
            }
            __syncthreads();                                   // bar 3

            if (isnear) {
                float pSr = 0.f, pSg = 0.f, pSb = 0.f, pP = 1.f;
                if (nidx > 0) {
                    pSr = sm.sSr[nidx-1]; pSg = sm.sSg[nidx-1];
                    pSb = sm.sSb[nidx-1]; pP = sm.sP[nidx-1];
                }
                const float ir = rcpf(pP);
                const float gSr = (ESr - pSr) * ir;
                const float gSg = (ESg - pSg) * ir;
                const float gSb = (ESb - pSb) * ir;
                const float gP  = EP * ir;
                const float gcr = gP * lb.w, gcg = gP * lc.x, gcb = gP * lc.y;
                sm.n1[nidx] = make_float2(lb.y, -gP);
                sm.p0[nidx] = make_ulonglong2(pk2(lb.x, lb.x), pk2(gcr, gcr));
                sm.p1[nidx] = make_ulonglong2(pk2(gcg, gcg), pk2(gcb, gcb));
                sm.p2[nidx] = make_ulonglong2(pk2(gSr, gSr), pk2(gSg, gSg));
                sm.p3[nidx] = make_ulonglong2(pk2(gSb, gSb), pk2(gP, gP));
            }
            if (tid == 0) {
                const float tSr = sm.wsf2[16], tSg = sm.wsf2[17];
                const float tSb = sm.wsf2[18], tP  = sm.wsf2[19];
                if (ncnt > 0) {
                    const float lSr = sm.sSr[ncnt-1], lSg = sm.sSg[ncnt-1];
                    const float lSb = sm.sSb[ncnt-1], lP = sm.sP[ncnt-1];
                    const float ir = rcpf(lP);
                    sm.tailSr = (tSr - lSr) * ir;
                    sm.tailSg = (tSg - lSg) * ir;
                    sm.tailSb = (tSb - lSb) * ir;
                    sm.tailP  = tP * ir;
                } else {
                    sm.tailSr = tSr; sm.tailSg = tSg; sm.tailSb = tSb; sm.tailP = tP;
                }
            }
            __syncthreads();                                   // bar 4

            if (!dead) {
#pragma unroll 2
                for (int t = 0; t < ncnt; t++) {
                    const float4     f0 = sm.n0[t];
                    const float2     h  = sm.n1[t];
                    const ulonglong2 q0 = sm.p0[t];
                    const ulonglong2 q1 = sm.p1[t];
                    const ulonglong2 q2 = sm.p2[t];
                    const ulonglong2 q3 = sm.p3[t];
                    const float dx  = X - f0.x;
                    const float tq  = fmaf(f0.z, dx * dx, h.x);
                    const float cdx = f0.w * dx;
                    const float dy0 = Yf0 - f0.y, dy1 = Yf1 - f0.y;
                    const u64 dy2   = pk2(dy0, dy1);
                    const u64 inner = fma2(q0.x, dy2, pk2(cdx, cdx));
                    const u64 e2    = fma2(dy2, inner, pk2(tq, tq));
                    float e0, e1; upk2(e0, e1, e2);
                    const float a0 = fminf(fmaxf(ex2f(e0), 0.01f), 0.99f);
                    const float a1 = fminf(fmaxf(ex2f(e1), 0.01f), 0.99f);
                    const u64 a2 = pk2(a0, a1);
                    const u64 sR = fma2(a2, q0.y, q2.x);
                    const u64 sG = fma2(a2, q1.x, q2.y);
                    const u64 sB = fma2(a2, q1.y, q3.x);
                    CR2 = fma2(T2, sR, CR2);
                    CG2 = fma2(T2, sG, CG2);
                    CB2 = fma2(T2, sB, CB2);
                    const u64 u2 = fma2(a2, pk2(h.y, h.y), q3.y);
                    T2 = mul2(T2, u2);
                }
                CR2 = fma2(T2, pk2(sm.tailSr, sm.tailSr), CR2);
                CG2 = fma2(T2, pk2(sm.tailSg, sm.tailSg), CG2);
                CB2 = fma2(T2, pk2(sm.tailSb, sm.tailSb), CB2);
                T2 = mul2(T2, pk2(sm.tailP, sm.tailP));
                float T0f, T1f; upk2(T0f, T1f, T2);
                if (T0f < 1e-7f && T1f < 1e-7f) dead = true;
            }
            if (__syncthreads_count(dead ? 0 : 1) == 0) break;
        }

        float C00, C10, C01, C11, C02, C12;
        upk2(C00, C10, CR2);
        upk2(C01, C11, CG2);
        upk2(C02, C12, CB2);
        const int ob0 = (Xi * IMG_W + Yi0) * 3;
        out[ob0 + 0] = C00; out[ob0 + 1] = C01; out[ob0 + 2] = C02;
        const int ob1 = (Xi * IMG_W + Yi1) * 3;
        out[ob1 + 0] = C10; out[ob1 + 1] = C11; out[ob1 + 2] = C12;
    }
}

extern "C" void kernel_launch(void* const* d_in, const int* in_sizes, int n_in,
                              void* d_out, int out_size)
{
    const float* pos2d   = (const float*)d_in[0];
    const float* cov2d   = (const float*)d_in[1];
    const float* opacity = (const float*)d_in[2];
    const float* color   = (const float*)d_in[3];
    float* out = (float*)d_out;

    fused_kernel<<<NB, BLOCK>>>(pos2d, cov2d, opacity, color, out);
}

// round 17
// speedup vs baseline: 1.2630x; 1.2630x over previous
#include <cuda_runtime.h>
#include <cuda_bf16.h>

#define N_G   4096
#define IMG_W 512
#define TILE  64
#define BLOCK 256
#define NB    592                    // 148 x 4 blocks — all co-resident
#define NSUB  1024                   // 64 tiles x 16 subtiles (16x16 px)
#define NBUCK 1024
#define BCAP  64
#define EXPSCALE (-0.72134752044f)   // -0.5 * log2(e)
#define FTHR     (-6.64385619f)      // -2*log2(100)

typedef unsigned long long u64;

__device__ float4 g_geo[N_G];        // px, py, radius (binning)
__device__ float4 g_la [N_G];        // px, py, ca', cbc'
__device__ float4 g_lb [N_G];        // cd', log2(op), ha, r
__device__ float4 g_lc [N_G];        // g, b, hc, 0
__device__ int    g_hist[NBUCK];     // zeroed at end of each launch
__device__ u64    g_bkey[NBUCK * BCAP];

__device__ float4 t_la[64 * N_G], t_lb[64 * N_G], t_lc[64 * N_G];
__device__ int    t_cnt[64];
__device__ int    c3a[64][8];
__device__ int    t_ready[64];

__device__ unsigned g_bar;
__device__ unsigned g_q;

__device__ __forceinline__ float ex2f(float x) {
    float y; asm("ex2.approx.f32 %0, %1;" : "=f"(y) : "f"(x)); return y;
}
__device__ __forceinline__ float rcpf(float x) {
    float y; asm("rcp.approx.f32 %0, %1;" : "=f"(y) : "f"(x)); return y;
}
__device__ __forceinline__ u64 pk2(float lo, float hi) {
    u64 r; asm("mov.b64 %0, {%1, %2};" : "=l"(r) : "f"(lo), "f"(hi)); return r;
}
__device__ __forceinline__ void upk2(float& lo, float& hi, u64 v) {
    asm("mov.b64 {%0, %1}, %2;" : "=f"(lo), "=f"(hi) : "l"(v));
}
__device__ __forceinline__ u64 fma2(u64 a, u64 b, u64 c) {
    u64 d; asm("fma.rn.f32x2 %0, %1, %2, %3;" : "=l"(d) : "l"(a), "l"(b), "l"(c)); return d;
}
__device__ __forceinline__ u64 mul2(u64 a, u64 b) {
    u64 d; asm("mul.rn.f32x2 %0, %1, %2;" : "=l"(d) : "l"(a), "l"(b)); return d;
}
__device__ __forceinline__ int dbucket(float d) {
    int b = (int)((d - 0.1f) * 102.4f);
    return max(0, min(NBUCK - 1, b));
}

struct SM {
    float4     n0[BLOCK];            // px, py, ca', cbc'   (D: aliased)
    float2     n1[BLOCK];            // lop2, -gP
    ulonglong2 p0[BLOCK];            // cd2, (gP*colr)2     (D: aliased)
    ulonglong2 p1[BLOCK];            // (gP*colg)2, (gP*colb)2
    ulonglong2 p2[BLOCK];            // gapSr2, gapSg2
    ulonglong2 p3[BLOCK];            // gapSb2, gP2
    float      sSr[BLOCK], sSg[BLOCK], sSb[BLOCK], sP[BLOCK];
    int        wsum[8];
    float      wsf[32];
    int        item;
};

__device__ __forceinline__ int scan_bool(bool p, int* wsum, int& tot) {
    __syncthreads();
    const unsigned bits = __ballot_sync(0xffffffffu, p);
    const int lane = threadIdx.x & 31, wd = threadIdx.x >> 5;
    if (lane == 0) wsum[wd] = __popc(bits);
    __syncthreads();
    int off = 0, t = 0;
#pragma unroll
    for (int w = 0; w < 8; w++) { int c = wsum[w]; if (w < wd) off += c; t += c; }
    tot = t;
    return off + __popc(bits & ((1u << lane) - 1u));
}

__device__ __forceinline__ void grid_sync() {
    __syncthreads();
    if (threadIdx.x == 0) {
        __threadfence();
        unsigned v = atomicAdd(&g_bar, 1u);
        unsigned target = (v / NB + 1u) * NB;
        while (*(volatile unsigned*)&g_bar < target) { }
        __threadfence();
    }
    __syncthreads();
}

__global__ void __launch_bounds__(BLOCK, 4)
fused_kernel(const float* __restrict__ pos2d, const float* __restrict__ cov2d,
             const float* __restrict__ opacity, const float* __restrict__ color,
             float* __restrict__ out)
{
    __shared__ SM sm;
    const int tid = threadIdx.x;
    const int bid = blockIdx.x;
    const int lane = tid & 31, wd = tid >> 5;
    const unsigned FULL = 0xffffffffu;

    // ---------- Phase B: bucket scatter (blocks 0..15) + counter reset ---------
    if (bid < 16) {
        const int i = bid * BLOCK + tid;
        const float d = pos2d[i * 3 + 2];
        const int b = dbucket(d);
        const int slot = atomicAdd(&g_hist[b], 1);
        if (slot < BCAP)
            g_bkey[(b << 6) + slot] = ((u64)__float_as_uint(d) << 32) | (unsigned)i;
    } else if (bid == 16) {
        for (int k = tid; k < 64 * 8; k += BLOCK) ((int*)c3a)[k] = 0;
        for (int k = tid; k < 64; k += BLOCK) t_ready[k] = 0;
        if (tid == 0) g_q = 0;
    }
    grid_sync();

    // ---------- Phase D: prefix + exact rank + params + bins (blocks 0..255) ---
    if (bid < 256) {
        int* s_h  = (int*)sm.n0;    // 1024 ints
        int* s_bs = (int*)sm.p0;    // 1024 ints
        for (int k = tid; k < NBUCK; k += BLOCK) s_h[k] = min(g_hist[k], BCAP);
        __syncthreads();
        const int t4 = tid * 4;
        const int h0 = s_h[t4], h1 = s_h[t4+1], h2 = s_h[t4+2], h3 = s_h[t4+3];
        const int sum4 = h0 + h1 + h2 + h3;
        int inc = sum4;
#pragma unroll
        for (int d = 1; d < 32; d <<= 1) {
            const int u = __shfl_up_sync(FULL, inc, d);
            if (lane >= d) inc += u;
        }
        if (lane == 31) sm.wsum[wd] = inc;
        __syncthreads();
        int woff = 0;
#pragma unroll
        for (int w = 0; w < 8; w++) if (w < wd) woff += sm.wsum[w];
        const int excl = woff + inc - sum4;
        s_bs[t4]     = excl;
        s_bs[t4 + 1] = excl + h0;
        s_bs[t4 + 2] = excl + h0 + h1;
        s_bs[t4 + 3] = excl + h0 + h1 + h2;
        __syncthreads();

        if (tid < 16) {
            const int i = bid * 16 + tid;
            const float dep = pos2d[i * 3 + 2];
            const u64 ki = ((u64)__float_as_uint(dep) << 32) | (unsigned)i;
            const int bk = dbucket(dep);
            const int cnt = s_h[bk];
            int rank = s_bs[bk];
#pragma unroll 4
            for (int j = 0; j < cnt; j++)
                rank += (g_bkey[(bk << 6) + j] < ki) ? 1 : 0;

            const float a = cov2d[i * 4 + 0];
            const float b = cov2d[i * 4 + 1];
            const float c = cov2d[i * 4 + 2];
            const float d = cov2d[i * 4 + 3];
            const float trace = a + d;
            const float det   = a * d - b * c;
            const float term2 = 0.5f * sqrtf(fmaxf(trace * trace - 4.0f * det, 0.0f));
            const float radius = 3.0f * sqrtf(fmaxf(0.5f * trace - term2, 0.5f * trace + term2));
            const float inv_det = 1.0f / det;

            const float px = pos2d[i * 3 + 0];
            const float py = pos2d[i * 3 + 1];
            const float lop2 = __log2f(opacity[i]);
            const float cr = fmaxf(color[i * 3 + 0] + 0.5f, 0.0f);
            const float cg = fmaxf(color[i * 3 + 1] + 0.5f, 0.0f);
            const float cb = fmaxf(color[i * 3 + 2] + 0.5f, 0.0f);

            const float cap  = EXPSCALE * d * inv_det;
            const float cbcp = EXPSCALE * -(b + c) * inv_det;
            const float cdp  = EXPSCALE * a * inv_det;
            const float hc = 0.5f * (b + c) / a;
            const float ha = 0.5f * (b + c) / d;

            g_geo[rank] = make_float4(px, py, radius, 0.0f);
            g_la [rank] = make_float4(px, py, cap, cbcp);
            g_lb [rank] = make_float4(cdp, lop2, ha, cr);
            g_lc [rank] = make_float4(cg, cb, hc, 0.0f);

            const int ch = rank >> 9;
            const int tx0 = max(0, (int)floorf((px - radius) * (1.f / 64.f)) - 1);
            const int tx1 = min(7, (int)floorf((px + radius) * (1.f / 64.f)) + 1);
            const int ty0 = max(0, (int)floorf((py - radius) * (1.f / 64.f)) - 1);
            const int ty1 = min(7, (int)floorf((py + radius) * (1.f / 64.f)) + 1);
            for (int tx = tx0; tx <= tx1; tx++) {
                const float left = (float)(tx * TILE);
                if (!((px + radius >= left) && (px - radius < left + (float)TILE))) continue;
                for (int ty = ty0; ty <= ty1; ty++) {
                    const float top = (float)(ty * TILE);
                    if ((py + radius >= top) && (py - radius < top + (float)TILE))
                        atomicAdd(&c3a[(tx << 3) | ty][ch], 1);
                }
            }
        }
    }
    grid_sync();

    // ---------- Phase 3: ordered compaction (blocks 0..511); 512 zeroes hist ---
    if (bid < 512) {
        const int tile = bid >> 3, ch = bid & 7;
        const float left = (float)((tile >> 3) * TILE);
        const float top  = (float)((tile & 7) * TILE);
        int offset = 0, total = 0;
#pragma unroll
        for (int c = 0; c < 8; c++) {
            const int cc = c3a[tile][c];
            if (c < ch) offset += cc;
            total += cc;
        }
        if (ch == 0 && tid == 0) t_cnt[tile] = total;
        int outbase = offset;
#pragma unroll
        for (int r = 0; r < 2; r++) {
            const int g = ch * 512 + r * 256 + tid;
            const float4 geo = g_geo[g];
            const bool v = (geo.x + geo.z >= left) && (geo.x - geo.z < left + (float)TILE) &&
                           (geo.y + geo.z >= top)  && (geo.y - geo.z < top  + (float)TILE);
            int tot;
            const int pos = scan_bool(v, sm.wsum, tot);
            if (v) {
                const int o = tile * N_G + outbase + pos;
                t_la[o] = g_la[g];
                t_lb[o] = g_lb[g];
                t_lc[o] = g_lc[g];
            }
            outbase += tot;
        }
        __syncthreads();
        if (tid == 0) {
            __threadfence();
            atomicAdd(&t_ready[tile], 1);
        }
    } else if (bid == 512) {
        for (int k = tid; k < NBUCK; k += BLOCK) g_hist[k] = 0;
    }

    // ---------- Phase 4: work-stealing render over 1024 subtiles (16x16) -------
    for (;;) {
        __syncthreads();
        if (tid == 0) sm.item = (int)atomicAdd(&g_q, 1u);
        __syncthreads();
        const int sub = sm.item;
        if (sub >= NSUB) break;

        const int ptile = sub >> 4, si = sub & 15;
        if (tid == 0) {
            while (*(volatile int*)&t_ready[ptile] < 8) __nanosleep(64);
            __threadfence();
        }
        __syncthreads();

        const int X0 = (ptile >> 3) * TILE + (si >> 2) * 16;
        const int Y0 = (ptile & 7) * TILE + (si & 3) * 16;
        const float rx0 = (float)X0, rx1 = (float)(X0 + 15);
        const float ry0 = (float)Y0, ry1 = (float)(Y0 + 15);

        const bool px_active = tid < 128;
        const int Xi  = X0 + (tid >> 3);
        const int Yi0 = Y0 + (tid & 7);
        const int Yi1 = Yi0 + 8;
        const float X = (float)Xi, Yf0 = (float)Yi0, Yf1 = (float)Yi1;

        const int cnt = t_cnt[ptile];
        const float4* __restrict__ LA = t_la + ptile * N_G;
        const float4* __restrict__ LB = t_lb + ptile * N_G;
        const float4* __restrict__ LC = t_lc + ptile * N_G;

        u64 T2  = pk2(1.f, 1.f);
        u64 CR2 = pk2(0.f, 0.f), CG2 = CR2, CB2 = CR2;
        bool dead = !px_active;

        for (int c0 = 0; c0 < cnt; c0 += BLOCK) {
            const int L = cnt - c0;
            const bool validg = tid < L;
            float4 la = make_float4(0,0,0,0), lb = make_float4(0,0,0,0), lc = make_float4(0,0,0,0);
            bool isfar = false;
            if (validg) {
                la = LA[c0 + tid]; lb = LB[c0 + tid]; lc = LC[c0 + tid];
                const float dxlo = rx0 - la.x, dxhi = rx1 - la.x;
                const float dylo = ry0 - la.y, dyhi = ry1 - la.y;
                const bool inside = (dxlo <= 0.f) && (dxhi >= 0.f) &&
                                    (dylo <= 0.f) && (dyhi >= 0.f);
                float qsm = 0.0f;
                if (!inside) {
                    const float hc = lc.z, ha = lb.z;
                    float dys = fminf(fmaxf(hc * dxlo, dylo), dyhi);
                    qsm = fmaf(fmaf(la.w, dys, la.z * dxlo), dxlo, lb.x * dys * dys);
                    dys = fminf(fmaxf(hc * dxhi, dylo), dyhi);
                    qsm = fmaxf(qsm, fmaf(fmaf(la.w, dys, la.z * dxhi), dxhi, lb.x * dys * dys));
                    float dxs = fminf(fmaxf(ha * dylo, dxlo), dxhi);
                    qsm = fmaxf(qsm, fmaf(fmaf(la.w, dxs, lb.x * dylo), dylo, la.z * dxs * dxs));
                    dxs = fminf(fmaxf(ha * dyhi, dxlo), dxhi);
                    qsm = fmaxf(qsm, fmaf(fmaf(la.w, dxs, lb.x * dyhi), dyhi, la.z * dxs * dxs));
                }
                isfar = qsm < (FTHR - lb.y);
            }
            const bool isnear = validg && !isfar;

            float aSr = 0.f, aSg = 0.f, aSb = 0.f, aP = 1.f;
            if (isfar) { aSr = 0.01f * lb.w; aSg = 0.01f * lc.x; aSb = 0.01f * lc.y; aP = 0.99f; }

            float vSr = aSr, vSg = aSg, vSb = aSb, vP = aP;
#pragma unroll
            for (int d = 1; d < 32; d <<= 1) {
                const float uSr = __shfl_up_sync(FULL, vSr, d);
                const float uSg = __shfl_up_sync(FULL, vSg, d);
                const float uSb = __shfl_up_sync(FULL, vSb, d);
                const float uP  = __shfl_up_sync(FULL, vP,  d);
                if (lane >= d) {
                    vSr = fmaf(uP, vSr, uSr);
                    vSg = fmaf(uP, vSg, uSg);
                    vSb = fmaf(uP, vSb, uSb);
                    vP *= uP;
                }
            }
            const unsigned nbits = __ballot_sync(FULL, isnear);
            if (lane == 31) {
                sm.wsf[wd*4+0] = vSr; sm.wsf[wd*4+1] = vSg;
                sm.wsf[wd*4+2] = vSb; sm.wsf[wd*4+3] = vP;
                sm.wsum[wd] = __popc(nbits);
            }
            __syncthreads();                                   // bar 1

            // every thread combines the 8 warp aggregates (no serial warp0 hop)
            float oSr = 0.f, oSg = 0.f, oSb = 0.f, oP = 1.f;
            float tSr = 0.f, tSg = 0.f, tSb = 0.f, tP = 1.f;
            int ioff = 0, ncnt = 0;
#pragma unroll
            for (int w = 0; w < 8; w++) {
                const float w0 = sm.wsf[w*4+0], w1 = sm.wsf[w*4+1];
                const float w2 = sm.wsf[w*4+2], wp = sm.wsf[w*4+3];
                const int wc = sm.wsum[w];
                if (w < wd) {
                    oSr = fmaf(oP, w0, oSr); oSg = fmaf(oP, w1, oSg);
                    oSb = fmaf(oP, w2, oSb); oP *= wp;
                    ioff += wc;
                }
                tSr = fmaf(tP, w0, tSr); tSg = fmaf(tP, w1, tSg);
                tSb = fmaf(tP, w2, tSb); tP *= wp;
                ncnt += wc;
            }
            float eSr = __shfl_up_sync(FULL, vSr, 1);
            float eSg = __shfl_up_sync(FULL, vSg, 1);
            float eSb = __shfl_up_sync(FULL, vSb, 1);
            float eP  = __shfl_up_sync(FULL, vP,  1);
            if (lane == 0) { eSr = 0.f; eSg = 0.f; eSb = 0.f; eP = 1.f; }
            const float ESr = fmaf(oP, eSr, oSr);
            const float ESg = fmaf(oP, eSg, oSg);
            const float ESb = fmaf(oP, eSb, oSb);
            const float EP  = oP * eP;

            const int nidx = ioff + __popc(nbits & ((1u << lane) - 1u));
            if (isnear) {
                sm.sSr[nidx] = ESr; sm.sSg[nidx] = ESg; sm.sSb[nidx] = ESb; sm.sP[nidx] = EP;
                sm.n0[nidx] = la;
            }
            __syncthreads();                                   // bar 2

            if (isnear) {
                float pSr = 0.f, pSg = 0.f, pSb = 0.f, pP = 1.f;
                if (nidx > 0) {
                    pSr = sm.sSr[nidx-1]; pSg = sm.sSg[nidx-1];
                    pSb = sm.sSb[nidx-1]; pP = sm.sP[nidx-1];
                }
                const float ir = rcpf(pP);
                const float gSr = (ESr - pSr) * ir;
                const float gSg = (ESg - pSg) * ir;
                const float gSb = (ESb - pSb) * ir;
                const float gP  = EP * ir;
                const float gcr = gP * lb.w, gcg = gP * lc.x, gcb = gP * lc.y;
                sm.n1[nidx] = make_float2(lb.y, -gP);
                sm.p0[nidx] = make_ulonglong2(pk2(lb.x, lb.x), pk2(gcr, gcr));
                sm.p1[nidx] = make_ulonglong2(pk2(gcg, gcg), pk2(gcb, gcb));
                sm.p2[nidx] = make_ulonglong2(pk2(gSr, gSr), pk2(gSg, gSg));
                sm.p3[nidx] = make_ulonglong2(pk2(gSb, gSb), pk2(gP, gP));
            }
            // per-thread tail (uses sSr[ncnt-1], valid after bar 2)
            float tlSr, tlSg, tlSb, tlP;
            if (ncnt > 0) {
                const float lS0 = sm.sSr[ncnt-1], lS1 = sm.sSg[ncnt-1];
                const float lS2 = sm.sSb[ncnt-1], lPP = sm.sP[ncnt-1];
                const float ir = rcpf(lPP);
                tlSr = (tSr - lS0) * ir;
                tlSg = (tSg - lS1) * ir;
                tlSb = (tSb - lS2) * ir;
                tlP  = tP * ir;
            } else {
                tlSr = tSr; tlSg = tSg; tlSb = tSb; tlP = tP;
            }
            __syncthreads();                                   // bar 3 (events visible)

            if (!dead) {
#pragma unroll 2
                for (int t = 0; t < ncnt; t++) {
                    const float4     f0 = sm.n0[t];
                    const float2     h  = sm.n1[t];
                    const ulonglong2 q0 = sm.p0[t];
                    const ulonglong2 q1 = sm.p1[t];
                    const ulonglong2 q2 = sm.p2[t];
                    const ulonglong2 q3 = sm.p3[t];
                    const float dx  = X - f0.x;
                    const float tq  = fmaf(f0.z, dx * dx, h.x);
                    const float cdx = f0.w * dx;
                    const float dy0 = Yf0 - f0.y, dy1 = Yf1 - f0.y;
                    const u64 dy2   = pk2(dy0, dy1);
                    const u64 inner = fma2(q0.x, dy2, pk2(cdx, cdx));
                    const u64 e2    = fma2(dy2, inner, pk2(tq, tq));
                    float e0, e1; upk2(e0, e1, e2);
                    const float a0 = fminf(fmaxf(ex2f(e0), 0.01f), 0.99f);
                    const float a1 = fminf(fmaxf(ex2f(e1), 0.01f), 0.99f);
                    const u64 a2 = pk2(a0, a1);
                    const u64 sR = fma2(a2, q0.y, q2.x);
                    const u64 sG = fma2(a2, q1.x, q2.y);
                    const u64 sB = fma2(a2, q1.y, q3.x);
                    CR2 = fma2(T2, sR, CR2);
                    CG2 = fma2(T2, sG, CG2);
                    CB2 = fma2(T2, sB, CB2);
                    const u64 u2 = fma2(a2, pk2(h.y, h.y), q3.y);
                    T2 = mul2(T2, u2);
                }
                CR2 = fma2(T2, pk2(tlSr, tlSr), CR2);
                CG2 = fma2(T2, pk2(tlSg, tlSg), CG2);
                CB2 = fma2(T2, pk2(tlSb, tlSb), CB2);
                T2 = mul2(T2, pk2(tlP, tlP));
                float T0f, T1f; upk2(T0f, T1f, T2);
                if (T0f < 1e-7f && T1f < 1e-7f) dead = true;
            }
            if (__syncthreads_count(dead ? 0 : 1) == 0) break;  // chunk boundary
        }

        if (px_active) {
            float C00, C10, C01, C11, C02, C12;
            upk2(C00, C10, CR2);
            upk2(C01, C11, CG2);
            upk2(C02, C12, CB2);
            const int ob0 = (Xi * IMG_W + Yi0) * 3;
            out[ob0 + 0] = C00; out[ob0 + 1] = C01; out[ob0 + 2] = C02;
            const int ob1 = (Xi * IMG_W + Yi1) * 3;
            out[ob1 + 0] = C10; out[ob1 + 1] = C11; out[ob1 + 2] = C12;
        }
    }
}

extern "C" void kernel_launch(void* const* d_in, const int* in_sizes, int n_in,
                              void* d_out, int out_size)
{
    const float* pos2d   = (const float*)d_in[0];
    const float* cov2d   = (const float*)d_in[1];
    const float* opacity = (const float*)d_in[2];
    const float* color   = (const float*)d_in[3];
    float* out = (float*)d_out;

    fused_kernel<<<NB, BLOCK>>>(pos2d, cov2d, opacity, color, out);
}